// round 15
// baseline (speedup 1.0000x reference)
#include <cuda_runtime.h>
#include <math.h>

// Problem constants
#define N_CAPS 64
#define CAPS_DIM 16
#define OUT_DIM 128
#define P_DIM 1152
#define BATCH 256
#define BO (BATCH * OUT_DIM)       // 32768
#define BO4 (BO / 4)               // 8192 float4 per p-row
#define WROW 132                   // padded row stride

#define THREADS 256
#define NB_W 4
#define KSPLIT 3                   // 3 stream blocks per batch
#define ROWS_PER_K (P_DIM / KSPLIT)   // 384
#define ITER_S (ROWS_PER_K / 8)       // 48 rows per warp
#define NB_X (BATCH * KSPLIT)      // 768
#define NBLK (NB_W + NB_X)         // 772 (all co-resident at 6 blocks/SM)

// Scratch (no cudaMalloc allowed)
__device__ __align__(16) float g_part[BATCH * KSPLIT * OUT_DIM];  // 384 KB
__device__ __align__(16) float g_wsum[N_CAPS * OUT_DIM];          // 32 KB
__device__ int g_done[BATCH];     // per-batch completed stream blocks (3)
__device__ int g_wflag;           // wsum blocks done (4)
__device__ int g_exit;            // epilogue blocks done -> reset

// ---------------------------------------------------------------------------
// 772 blocks x 256 threads (~42 warps/SM — the shape that hit 82% HBM).
//  bids 0..3    : Wsum
//  bids 4..771  : (b, k) stream blocks; k==2 also runs batch b's routing
//                 epilogue (256-thread wide) after its partners' partials land.
// ---------------------------------------------------------------------------
__global__ void __launch_bounds__(THREADS, 6) capsule_fused(
    const float4* __restrict__ x4,        // (1152, 256, 128) fp32
    const float4* __restrict__ w4,        // (64, 16, 128) fp32
    float* __restrict__ out)              // (256, 1, 128)
{
    const int bid  = blockIdx.x;
    const int t    = threadIdx.x;
    const int g    = t >> 5;      // warp 0..7
    const int lane = t & 31;

    // ---------------- wsum blocks ----------------
    if (bid < NB_W) {
#pragma unroll
        for (int r = 0; r < 2; ++r) {
            int i4 = bid * 512 + r * 256 + t;            // 0..2047
            int n  = i4 >> 5;
            int o4 = i4 & 31;
            const float4* base = w4 + (size_t)n * (CAPS_DIM * OUT_DIM / 4) + o4;
            float4 acc = make_float4(0.f, 0.f, 0.f, 0.f);
#pragma unroll
            for (int c = 0; c < CAPS_DIM; ++c) {
                float4 v = __ldg(&base[c * (OUT_DIM / 4)]);
                acc.x += v.x; acc.y += v.y; acc.z += v.z; acc.w += v.w;
            }
            reinterpret_cast<float4*>(g_wsum)[i4] = acc;
        }
        __threadfence();
        __syncthreads();
        if (t == 0) atomicAdd(&g_wflag, 1);
        return;
    }

    // ---------------- stream blocks ----------------
    const int idx = bid - NB_W;       // 0..767
    const int b   = idx / KSPLIT;
    const int k   = idx % KSPLIT;

    // sh_w doubles as sh_red early (sh_red dead before sh_w is staged)
    __shared__ __align__(16) float sh_w[N_CAPS * WROW];   // 33.8 KB
    __shared__ __align__(16) float shS[2 * OUT_DIM];      // col-pass halves
    __shared__ __align__(16) float shrp0[OUT_DIM];
    __shared__ float shpart[256];
    __shared__ float shc[N_CAPS];
    __shared__ float shred[4];

    float (*sh_red)[OUT_DIM] = reinterpret_cast<float(*)[OUT_DIM]>(sh_w);

    // Stream 384 rows of batch b's 512B column slice: warp g reads rows
    // k*384 + g, +8, ... (48 iterations, barrier-free)
    {
        const float4* base = x4 + (size_t)(k * ROWS_PER_K + g) * BO4 + b * 32 + lane;
        float4 acc = make_float4(0.f, 0.f, 0.f, 0.f);
#pragma unroll 8
        for (int i = 0; i < ITER_S; ++i) {
            float4 v = __ldcs(&base[(size_t)i * 8 * BO4]);
            acc.x += v.x; acc.y += v.y; acc.z += v.z; acc.w += v.w;
        }
        *reinterpret_cast<float4*>(&sh_red[g][lane * 4]) = acc;
    }
    __syncthreads();

    // Combine 8 warp partials -> g_part[(b,k)][:]
    if (t < 128) {
        float p = 0.f;
#pragma unroll
        for (int gg = 0; gg < 8; ++gg)
            p += sh_red[gg][t];
        g_part[(b * KSPLIT + k) * OUT_DIM + t] = p;
    }
    __threadfence();
    __syncthreads();
    if (t == 0) atomicAdd(&g_done[b], 1);

    if (k != 2) return;               // only k==2 runs the epilogue

    // ---------------- routing epilogue (256 threads) ----------------
    if (t == 0) {
        volatile int* wf = &g_wflag;
        while (*wf < NB_W) __nanosleep(32);
        volatile int* dn = &g_done[b];
        while (*dn < KSPLIT) __nanosleep(32);
    }
    __syncthreads();
    __threadfence();                  // acquire g_wsum + partner partials

    // Stage W into padded shared (8 float4/thread, batched)
    {
        float4 wv[8];
        const float4* gw4 = reinterpret_cast<const float4*>(g_wsum);
#pragma unroll
        for (int kk = 0; kk < 8; ++kk)
            wv[kk] = __ldg(&gw4[t + kk * 256]);
#pragma unroll
        for (int kk = 0; kk < 8; ++kk) {
            int i4 = t + kk * 256;
            int n  = i4 >> 5;
            int o  = (i4 & 31) * 4;
            *reinterpret_cast<float4*>(&sh_w[n * WROW + o]) = wv[kk];
        }
    }

    const int o  = t & 127;           // o index (duplicated across halves)
    const int nh = t >> 7;            // n-half for the col pass

    // X[o] from the 3 partials (L2-hot)
    float X = g_part[(b * KSPLIT + 0) * OUT_DIM + o]
            + g_part[(b * KSPLIT + 1) * OUT_DIM + o]
            + g_part[(b * KSPLIT + 2) * OUT_DIM + o];

    if (t < N_CAPS) shc[t] = 1.0f / N_CAPS;
    float logit_a = 0.f, logit_b = 0.f;   // warp 0: caps lane, lane+32
    __syncthreads();

    float s = 0.f, scale = 0.f;
    for (int iter = 0; iter < 3; ++iter) {
        // col pass split by n-half: 32 FFMA each, 4 accumulators
        {
            float a0 = 0.f, a1 = 0.f, a2 = 0.f, a3 = 0.f;
            const float* wp = &sh_w[(nh * 32) * WROW + o];
            const float* cp = &shc[nh * 32];
#pragma unroll
            for (int j = 0; j < 8; ++j) {
                a0 += cp[4 * j + 0] * wp[(4 * j + 0) * WROW];
                a1 += cp[4 * j + 1] * wp[(4 * j + 1) * WROW];
                a2 += cp[4 * j + 2] * wp[(4 * j + 2) * WROW];
                a3 += cp[4 * j + 3] * wp[(4 * j + 3) * WROW];
            }
            shS[nh * OUT_DIM + o] = (a0 + a1) + (a2 + a3);
        }
        __syncthreads();

        s = (shS[o] + shS[OUT_DIM + o]) * X;

        // norm reduce on t<128 only (each o counted once)
        if (t < 128) {
            float sq = s * s;
#pragma unroll
            for (int off = 16; off > 0; off >>= 1)
                sq += __shfl_xor_sync(0xffffffffu, sq, off);
            if (lane == 0) shred[t >> 5] = sq;
            shrp0[o] = s * X;          // pre-scale routed vector
        }
        __syncthreads();

        float tot = shred[0] + shred[1] + shred[2] + shred[3];
        scale = sqrtf(tot) / (1.0f + tot);    // norm / (1 + norm^2)

        if (iter == 2) break;

        // logits partial: cap n = t&63, o-quarter q = t>>6 (8 LDS.128 each)
        {
            int n_id = t & 63, q = t >> 6;
            const float4* wrow = reinterpret_cast<const float4*>(&sh_w[n_id * WROW]) + q * 8;
            const float4* rp4  = reinterpret_cast<const float4*>(shrp0) + q * 8;
            float acc = 0.f;
#pragma unroll
            for (int j = 0; j < 8; ++j) {
                float4 w4v = wrow[j];
                float4 r4v = rp4[j];
                acc += w4v.x * r4v.x + w4v.y * r4v.y + w4v.z * r4v.z + w4v.w * r4v.w;
            }
            shpart[t] = scale * acc;   // index q*64 + n
        }
        __syncthreads();

        // warp 0: logits (2 caps/lane, 4 quarters each) + in-warp softmax
        if (t < 32) {
            logit_a += shpart[t]      + shpart[t + 64]
                     + shpart[t + 128] + shpart[t + 192];
            logit_b += shpart[t + 32] + shpart[t + 96]
                     + shpart[t + 160] + shpart[t + 224];
            float m = fmaxf(logit_a, logit_b);
#pragma unroll
            for (int off = 16; off > 0; off >>= 1)
                m = fmaxf(m, __shfl_xor_sync(0xffffffffu, m, off));
            float ea  = __expf(logit_a - m);
            float eb2 = __expf(logit_b - m);
            float sm  = ea + eb2;
#pragma unroll
            for (int off = 16; off > 0; off >>= 1)
                sm += __shfl_xor_sync(0xffffffffu, sm, off);
            float inv = 1.0f / sm;
            shc[t]      = ea * inv;
            shc[t + 32] = eb2 * inv;
        }
        __syncthreads();
    }

    if (t < 128) out[b * OUT_DIM + o] = scale * s;   // final squash

    // reset for graph replay (runs after all epilogue reads)
    if (t == 0) {
        __threadfence();
        int v = atomicAdd(&g_exit, 1);
        if (v == BATCH - 1) {
            for (int i = 0; i < BATCH; ++i) g_done[i] = 0;
            g_wflag = 0;
            __threadfence();
            g_exit = 0;
            __threadfence();
        }
    }
}

// ---------------------------------------------------------------------------
extern "C" void kernel_launch(void* const* d_in, const int* in_sizes, int n_in,
                              void* d_out, int out_size) {
    const float* x = (const float*)d_in[0];             // (1152, 256, 128)
    const float* w = (const float*)d_in[1];             // (64, 16, 128)
    float* out = (float*)d_out;                         // (256, 1, 128)

    capsule_fused<<<NBLK, THREADS>>>(reinterpret_cast<const float4*>(x),
                                     reinterpret_cast<const float4*>(w),
                                     out);
}

// round 16
// speedup vs baseline: 1.3150x; 1.3150x over previous
#include <cuda_runtime.h>
#include <math.h>

// Problem constants
#define N_CAPS 64
#define CAPS_DIM 16
#define OUT_DIM 128
#define P_DIM 1152
#define BATCH 256
#define BO (BATCH * OUT_DIM)       // 32768
#define BO4 (BO / 4)               // 8192 float4 per p-row
#define WROW 132                   // padded row stride (float4-aligned)

#define THREADS 512
#define NB_W 4                     // wsum blocks (bids 0..3)
#define NB_X 256                   // one block per batch element
#define NBLK (NB_W + NB_X)         // 260 — all co-resident (no 2nd wave)
#define ROWS_PER_WARP (P_DIM / 16) // 72 contiguous rows per warp

// Scratch (no cudaMalloc allowed)
__device__ __align__(16) float g_wsum[N_CAPS * OUT_DIM];   // 32 KB
__device__ int g_wflag;   // wsum blocks done (target NB_W)
__device__ int g_xdone;   // x blocks done (target NB_X) -> resets counters

// ---------------------------------------------------------------------------
// Single fused kernel (R12 structure; stream loop now walks rows SEQUENTIALLY
// per warp for page/DRAM-row locality, like the 82%-HBM split reduce).
//  bids 0..3   : Wsum[n,o] = sum_c w[n,c,o]
//  bids 4..259 : batch b = bid-4: stream x[:, b, :] once from DRAM, reduce
//                over p, then routing epilogue in-block (warps 4..15 exit).
// ---------------------------------------------------------------------------
__global__ void __launch_bounds__(THREADS, 2) capsule_fused(
    const float4* __restrict__ x4,        // (1152, 256, 128) fp32
    const float4* __restrict__ w4,        // (64, 16, 128) fp32
    float* __restrict__ out)              // (256, 1, 128)
{
    const int bid = blockIdx.x;
    const int t   = threadIdx.x;

    // ---------------- wsum blocks ----------------
    if (bid < NB_W) {
        int i4 = bid * THREADS + t;                      // 0..2047
        int n  = i4 >> 5;
        int o4 = i4 & 31;
        const float4* base = w4 + (size_t)n * (CAPS_DIM * OUT_DIM / 4) + o4;
        float4 acc = make_float4(0.f, 0.f, 0.f, 0.f);
#pragma unroll
        for (int c = 0; c < CAPS_DIM; ++c) {
            float4 v = __ldg(&base[c * (OUT_DIM / 4)]);
            acc.x += v.x; acc.y += v.y; acc.z += v.z; acc.w += v.w;
        }
        reinterpret_cast<float4*>(g_wsum)[i4] = acc;
        __threadfence();
        __syncthreads();
        if (t == 0) atomicAdd(&g_wflag, 1);
        return;
    }

    // ---------------- x blocks: stream + reduce + route ----------------
    const int b    = bid - NB_W;
    const int g    = t >> 5;      // warp 0..15
    const int o4   = t & 31;      // float4 column within the batch slice
    const int lane = t & 31;
    const int wid  = t >> 5;

    __shared__ __align__(16) float sh_red[16][OUT_DIM];    // 8 KB group partials
    __shared__ __align__(16) float sh_w[N_CAPS * WROW];    // 33.8 KB padded Wsum
    __shared__ __align__(16) float shrp0[OUT_DIM];         // pre-scale routed vec
    __shared__ float shpart[128];
    __shared__ float shc[N_CAPS];
    __shared__ float shred[4];

    // Stream x[:, b, :]: warp g reads rows [g*72, (g+1)*72) SEQUENTIALLY
    // (1-row stride => block lives in few 2MB pages, like the split reduce)
    {
        const float4* base = x4 + (size_t)(g * ROWS_PER_WARP) * BO4 + b * 32 + o4;
        float4 acc = make_float4(0.f, 0.f, 0.f, 0.f);
#pragma unroll 8
        for (int i = 0; i < ROWS_PER_WARP; ++i) {         // 72 iterations
            float4 v = __ldcs(&base[(size_t)i * BO4]);
            acc.x += v.x; acc.y += v.y; acc.z += v.z; acc.w += v.w;
        }
        *reinterpret_cast<float4*>(&sh_red[g][o4 * 4]) = acc;
    }

    // Wait for wsum (long done by now)
    if (t == 0) {
        volatile int* f = &g_wflag;
        while (*f < NB_W) __nanosleep(32);
    }
    __syncthreads();          // publishes sh_red + orders after spin
    __threadfence();

    // Stage W to padded shared (all 512 threads, batched loads)
    {
        float4 wv[4];
        const float4* gw4 = reinterpret_cast<const float4*>(g_wsum);
#pragma unroll
        for (int k = 0; k < 4; ++k)
            wv[k] = __ldg(&gw4[t + k * THREADS]);
#pragma unroll
        for (int k = 0; k < 4; ++k) {
            int i4 = t + k * THREADS;
            int n  = i4 >> 5;
            int o  = (i4 & 31) * 4;
            *reinterpret_cast<float4*>(&sh_w[n * WROW + o]) = wv[k];
        }
    }
    if (t < N_CAPS) shc[t] = 1.0f / N_CAPS;
    __syncthreads();          // sh_w + shc visible

    // Exit bookkeeping on a departing warp (runs once per block)
    if (t == 256) {
        __threadfence();
        int v = atomicAdd(&g_xdone, 1);
        if (v == NB_X - 1) {
            g_wflag = 0;
            g_xdone = 0;
            __threadfence();
        }
    }
    if (wid >= 4) return;     // 12 warps exit; epilogue barriers = 4 warps

    // Finalize X[o]: sum the 16 group partials
    float X = 0.f;
#pragma unroll
    for (int gg = 0; gg < 16; ++gg)
        X += sh_red[gg][t];

    float logit_a = 0.f, logit_b = 0.f;   // warp 0: caps lane, lane+32

    // ---------------- routing: 2 updates + final squash, 3 BAR/iter --------
    for (int iter = 0; iter < 3; ++iter) {
        // s_o = X * sum_n c_n W[n,o]  (column LDS, lanes consecutive)
        float s = 0.f;
#pragma unroll
        for (int n = 0; n < N_CAPS; ++n)
            s += shc[n] * sh_w[n * WROW + t];
        s *= X;

        // publish pre-scale rp AND norm partial before ONE sync
        float sq = s * s;
#pragma unroll
        for (int off = 16; off > 0; off >>= 1)
            sq += __shfl_xor_sync(0xffffffffu, sq, off);
        if (lane == 0) shred[wid] = sq;
        shrp0[t] = s * X;                      // pre-scale routed vector
        __syncthreads();

        float tot   = shred[0] + shred[1] + shred[2] + shred[3];
        float scale = sqrtf(tot) / (1.0f + tot);   // norm / (1 + norm^2)

        if (iter == 2) {
            out[b * OUT_DIM + t] = scale * s;      // final squash
            break;
        }

        // logits partial: cap (t&63), o-half (t>>6); scale folded in here
        {
            int n_id = t & 63, oh = t >> 6;
            const float4* wrow = reinterpret_cast<const float4*>(&sh_w[n_id * WROW]) + oh * 16;
            const float4* rp4  = reinterpret_cast<const float4*>(shrp0) + oh * 16;
            float acc = 0.f;
#pragma unroll
            for (int j = 0; j < 16; ++j) {
                float4 w4v = wrow[j];
                float4 r4v = rp4[j];
                acc += w4v.x * r4v.x + w4v.y * r4v.y + w4v.z * r4v.z + w4v.w * r4v.w;
            }
            shpart[t] = scale * acc;
        }
        __syncthreads();

        // warp 0: accumulate logits (2 caps/lane) + softmax fully in-warp
        if (t < 32) {
            logit_a += shpart[t]      + shpart[t + 64];
            logit_b += shpart[t + 32] + shpart[t + 96];
            float m = fmaxf(logit_a, logit_b);
#pragma unroll
            for (int off = 16; off > 0; off >>= 1)
                m = fmaxf(m, __shfl_xor_sync(0xffffffffu, m, off));
            float ea = __expf(logit_a - m);
            float eb = __expf(logit_b - m);
            float sm = ea + eb;
#pragma unroll
            for (int off = 16; off > 0; off >>= 1)
                sm += __shfl_xor_sync(0xffffffffu, sm, off);
            float inv = 1.0f / sm;
            shc[t]      = ea * inv;
            shc[t + 32] = eb * inv;
        }
        __syncthreads();
    }
}

// ---------------------------------------------------------------------------
extern "C" void kernel_launch(void* const* d_in, const int* in_sizes, int n_in,
                              void* d_out, int out_size) {
    const float* x = (const float*)d_in[0];             // (1152, 256, 128)
    const float* w = (const float*)d_in[1];             // (64, 16, 128)
    float* out = (float*)d_out;                         // (256, 1, 128)

    capsule_fused<<<NBLK, THREADS>>>(reinterpret_cast<const float4*>(x),
                                     reinterpret_cast<const float4*>(w),
                                     out);
}

// round 17
// speedup vs baseline: 1.3258x; 1.0082x over previous
#include <cuda_runtime.h>
#include <math.h>

// Problem constants
#define N_CAPS 64
#define CAPS_DIM 16
#define OUT_DIM 128
#define P_DIM 1152
#define BATCH 256
#define BO (BATCH * OUT_DIM)       // 32768
#define BO4 (BO / 4)               // 8192 float4 per p-row
#define WROW 132                   // padded row stride (float4-aligned)

#define THREADS 512
#define NB_W 4                     // wsum blocks (bids 0..3)
#define NB_X 256                   // one block per batch element
#define NBLK (NB_W + NB_X)         // 260 — all co-resident (no 2nd wave)

// Scratch (no cudaMalloc allowed)
__device__ __align__(16) float g_wsum[N_CAPS * OUT_DIM];   // 32 KB
__device__ int g_wflag;   // wsum blocks done (target NB_W)
__device__ int g_xdone;   // x blocks done (target NB_X) -> resets counters

// ---------------------------------------------------------------------------
// Single fused kernel (R12 stream; epilogue now WIDE — all 16 warps, 4/SMSP —
// because the epilogue is latency-bound and scales with warps/SMSP).
//  bids 0..3   : Wsum[n,o] = sum_c w[n,c,o]
//  bids 4..259 : batch b = bid-4: stream x[:, b, :] once from DRAM, reduce
//                over p, then 512-thread routing epilogue in-block.
// ---------------------------------------------------------------------------
__global__ void __launch_bounds__(THREADS, 2) capsule_fused(
    const float4* __restrict__ x4,        // (1152, 256, 128) fp32
    const float4* __restrict__ w4,        // (64, 16, 128) fp32
    float* __restrict__ out)              // (256, 1, 128)
{
    const int bid = blockIdx.x;
    const int t   = threadIdx.x;

    // ---------------- wsum blocks ----------------
    if (bid < NB_W) {
        int i4 = bid * THREADS + t;                      // 0..2047
        int n  = i4 >> 5;
        int o4 = i4 & 31;
        const float4* base = w4 + (size_t)n * (CAPS_DIM * OUT_DIM / 4) + o4;
        float4 acc = make_float4(0.f, 0.f, 0.f, 0.f);
#pragma unroll
        for (int c = 0; c < CAPS_DIM; ++c) {
            float4 v = __ldg(&base[c * (OUT_DIM / 4)]);
            acc.x += v.x; acc.y += v.y; acc.z += v.z; acc.w += v.w;
        }
        reinterpret_cast<float4*>(g_wsum)[i4] = acc;
        __threadfence();
        __syncthreads();
        if (t == 0) atomicAdd(&g_wflag, 1);
        return;
    }

    // ---------------- x blocks: stream + reduce + route ----------------
    const int b    = bid - NB_W;
    const int g    = t >> 5;      // warp 0..15
    const int o4   = t & 31;      // float4 column within the batch slice
    const int lane = t & 31;

    __shared__ __align__(16) float sh_red[16][OUT_DIM];    // 8 KB group partials
    __shared__ __align__(16) float sh_w[N_CAPS * WROW];    // 33.8 KB padded Wsum
    __shared__ __align__(16) float shS[4][OUT_DIM];        // col-pass quarters
    __shared__ __align__(16) float shrp0[OUT_DIM];         // pre-scale routed vec
    __shared__ float shpart[512];
    __shared__ float shc[N_CAPS];
    __shared__ float shred[4];

    // Stream x[:, b, :]: warp g reads rows g, g+16, ... (R12 pattern)
    {
        const float4* base = x4 + (size_t)g * BO4 + b * 32 + o4;
        float4 acc = make_float4(0.f, 0.f, 0.f, 0.f);
#pragma unroll 8
        for (int i = 0; i < P_DIM / 16; ++i) {            // 72 iterations
            float4 v = __ldcs(&base[(size_t)i * 16 * BO4]);
            acc.x += v.x; acc.y += v.y; acc.z += v.z; acc.w += v.w;
        }
        *reinterpret_cast<float4*>(&sh_red[g][o4 * 4]) = acc;
    }

    // Wait for wsum (long done by now)
    if (t == 0) {
        volatile int* f = &g_wflag;
        while (*f < NB_W) __nanosleep(32);
    }
    __syncthreads();          // publishes sh_red + orders after spin
    __threadfence();

    // Stage W to padded shared (batched loads, all 512 threads)
    {
        float4 wv[4];
        const float4* gw4 = reinterpret_cast<const float4*>(g_wsum);
#pragma unroll
        for (int k = 0; k < 4; ++k)
            wv[k] = __ldg(&gw4[t + k * THREADS]);
#pragma unroll
        for (int k = 0; k < 4; ++k) {
            int i4 = t + k * THREADS;
            int n  = i4 >> 5;
            int o  = (i4 & 31) * 4;
            *reinterpret_cast<float4*>(&sh_w[n * WROW + o]) = wv[k];
        }
    }
    if (t < N_CAPS) shc[t] = 1.0f / N_CAPS;
    __syncthreads();          // sh_w + shc visible

    // ---------------- WIDE routing epilogue (512 threads) ----------------
    const int o  = t & 127;   // o index (4 copies across n-quarters)
    const int nq = t >> 7;    // n-quarter 0..3 for the col pass

    // X[o] needed only by t<128 (s-combine / rp / out)
    float X = 0.f;
    if (t < 128) {
#pragma unroll
        for (int gg = 0; gg < 16; ++gg)
            X += sh_red[gg][o];
    }

    float logit_a = 0.f, logit_b = 0.f;   // warp 0: caps lane, lane+32
    float s = 0.f, scale = 0.f;

    for (int iter = 0; iter < 3; ++iter) {
        // col quarter: caps [nq*16, nq*16+16), 16 FFMA+LDS per thread
        {
            float a = 0.f;
            const float* cp = &shc[nq * 16];
            const float* wp = &sh_w[(nq * 16) * WROW + o];
#pragma unroll
            for (int j = 0; j < 16; ++j)
                a += cp[j] * wp[j * WROW];
            shS[nq][o] = a;
        }
        __syncthreads();

        if (t < 128) {
            s = (shS[0][o] + shS[1][o] + shS[2][o] + shS[3][o]) * X;
            float sq = s * s;
#pragma unroll
            for (int off = 16; off > 0; off >>= 1)
                sq += __shfl_xor_sync(0xffffffffu, sq, off);
            if (lane == 0) shred[t >> 5] = sq;
            shrp0[o] = s * X;                  // pre-scale routed vector
        }
        __syncthreads();

        float tot = shred[0] + shred[1] + shred[2] + shred[3];
        scale = sqrtf(tot) / (1.0f + tot);     // norm / (1 + norm^2)

        if (iter == 2) {
            if (t < 128) out[b * OUT_DIM + o] = scale * s;   // final squash
            break;
        }

        // logits eighth: cap n = t&63, o-eighth e = t>>6 (4 LDS.128 w + 4 rp)
        {
            int n_id = t & 63, e = t >> 6;
            const float4* wrow = reinterpret_cast<const float4*>(&sh_w[n_id * WROW]) + e * 4;
            const float4* rp4  = reinterpret_cast<const float4*>(shrp0) + e * 4;
            float acc = 0.f;
#pragma unroll
            for (int j = 0; j < 4; ++j) {
                float4 w4v = wrow[j];
                float4 r4v = rp4[j];
                acc += w4v.x * r4v.x + w4v.y * r4v.y + w4v.z * r4v.z + w4v.w * r4v.w;
            }
            shpart[t] = scale * acc;           // index e*64 + n
        }
        __syncthreads();

        // warp 0: sum 8 eighths per cap (2 caps/lane) + in-warp softmax
        if (t < 32) {
#pragma unroll
            for (int e = 0; e < 8; ++e) {
                logit_a += shpart[t +      e * 64];
                logit_b += shpart[t + 32 + e * 64];
            }
            float m = fmaxf(logit_a, logit_b);
#pragma unroll
            for (int off = 16; off > 0; off >>= 1)
                m = fmaxf(m, __shfl_xor_sync(0xffffffffu, m, off));
            float ea = __expf(logit_a - m);
            float eb = __expf(logit_b - m);
            float sm = ea + eb;
#pragma unroll
            for (int off = 16; off > 0; off >>= 1)
                sm += __shfl_xor_sync(0xffffffffu, sm, off);
            float inv = 1.0f / sm;
            shc[t]      = ea * inv;
            shc[t + 32] = eb * inv;
        }
        __syncthreads();
    }

    // Exit bookkeeping (once per block; safe: every block passed its wflag
    // wait ~20us before any block can reach this point)
    if (t == 0) {
        __threadfence();
        int v = atomicAdd(&g_xdone, 1);
        if (v == NB_X - 1) {
            g_wflag = 0;
            g_xdone = 0;
            __threadfence();
        }
    }
}

// ---------------------------------------------------------------------------
extern "C" void kernel_launch(void* const* d_in, const int* in_sizes, int n_in,
                              void* d_out, int out_size) {
    const float* x = (const float*)d_in[0];             // (1152, 256, 128)
    const float* w = (const float*)d_in[1];             // (64, 16, 128)
    float* out = (float*)d_out;                         // (256, 1, 128)

    capsule_fused<<<NBLK, THREADS>>>(reinterpret_cast<const float4*>(x),
                                     reinterpret_cast<const float4*>(w),
                                     out);
}